// round 11
// baseline (speedup 1.0000x reference)
#include <cuda_runtime.h>
#include <cstdint>

#define BATCH 16384
#define NEG 5
#define WARPS_PER_BLOCK 8
#define THREADS (WARPS_PER_BLOCK * 32)          // 256
#define NBLOCKS (BATCH / WARPS_PER_BLOCK)       // 2048

__device__ float g_partials[NBLOCKS];
__device__ unsigned int g_count;                // zero-init; last block resets

__device__ __forceinline__ float logsig(float x) {
    // stable log(sigmoid(x)) = min(x,0) - log1p(exp(-|x|))
    return fminf(x, 0.0f) - log1pf(expf(-fabsf(x)));
}

// 16B row-chunk load, non-coherent path, with an L2 evict_last cache-hint
// policy (pin gathered rows in L2 across graph replays: the same ~55MB row
// set is re-gathered every replay and fits in the 126MB L2).
__device__ __forceinline__ float4 ldg_evict_last(const float4* p, uint64_t pol) {
    float4 r;
    asm volatile("ld.global.nc.L2::cache_hint.v4.f32 {%0,%1,%2,%3}, [%4], %5;"
                 : "=f"(r.x), "=f"(r.y), "=f"(r.z), "=f"(r.w)
                 : "l"(p), "l"(pol));
    return r;
}

__global__ void __launch_bounds__(THREADS, 8)
sg_fused(const float* __restrict__ emb,
         const int* __restrict__ centers,
         const int* __restrict__ contexts,
         const int* __restrict__ negs,
         float* __restrict__ out) {
    const int lane = threadIdx.x & 31;
    const int warp = threadIdx.x >> 5;
    const int b = blockIdx.x * WARPS_PER_BLOCK + warp;

    const float4* e4 = reinterpret_cast<const float4*>(emb);

    uint64_t pol;
    asm("createpolicy.fractional.L2::evict_last.b64 %0, 1.0;" : "=l"(pol));

    const int ic = centers[b];
    const int it = contexts[b];
    const int in0 = negs[b * NEG + 0];
    const int in1 = negs[b * NEG + 1];
    const int in2 = negs[b * NEG + 2];
    const int in3 = negs[b * NEG + 3];
    const int in4 = negs[b * NEG + 4];

    // 7 independent 512B row gathers per warp, L2-pinned via cache hint.
    const float4 u  = ldg_evict_last(e4 + (size_t)ic  * 32 + lane, pol);
    const float4 v  = ldg_evict_last(e4 + (size_t)it  * 32 + lane, pol);
    const float4 w0 = ldg_evict_last(e4 + (size_t)in0 * 32 + lane, pol);
    const float4 w1 = ldg_evict_last(e4 + (size_t)in1 * 32 + lane, pol);
    const float4 w2 = ldg_evict_last(e4 + (size_t)in2 * 32 + lane, pol);
    const float4 w3 = ldg_evict_last(e4 + (size_t)in3 * 32 + lane, pol);
    const float4 w4 = ldg_evict_last(e4 + (size_t)in4 * 32 + lane, pol);

    // sum_k (u . nv_k) == u . (sum_k nv_k)
    float4 ns;
    ns.x = w0.x + w1.x + w2.x + w3.x + w4.x;
    ns.y = w0.y + w1.y + w2.y + w3.y + w4.y;
    ns.z = w0.z + w1.z + w2.z + w3.z + w4.z;
    ns.w = w0.w + w1.w + w2.w + w3.w + w4.w;

    float pos = u.x * v.x  + u.y * v.y  + u.z * v.z  + u.w * v.w;
    float neg = u.x * ns.x + u.y * ns.y + u.z * ns.z + u.w * ns.w;

    #pragma unroll
    for (int o = 16; o > 0; o >>= 1) {
        pos += __shfl_xor_sync(0xffffffffu, pos, o);
        neg += __shfl_xor_sync(0xffffffffu, neg, o);
    }

    __shared__ float sm[WARPS_PER_BLOCK];
    __shared__ bool is_last;
    if (lane == 0)
        sm[warp] = logsig(pos) + logsig(-neg);
    __syncthreads();

    if (threadIdx.x == 0) {
        float s = 0.0f;
        #pragma unroll
        for (int i = 0; i < WARPS_PER_BLOCK; i++) s += sm[i];
        g_partials[blockIdx.x] = s;
        __threadfence();
        unsigned int t = atomicAdd(&g_count, 1u);
        is_last = (t == NBLOCKS - 1);
    }
    __syncthreads();

    // Last block: deterministic fixed-order reduction of 2048 partials.
    if (is_last) {
        __shared__ float red[THREADS];
        float s = 0.0f;
        #pragma unroll
        for (int i = 0; i < NBLOCKS / THREADS; i++)     // 8 per thread
            s += g_partials[threadIdx.x + i * THREADS];
        red[threadIdx.x] = s;
        __syncthreads();
        #pragma unroll
        for (int o = THREADS / 2; o > 0; o >>= 1) {
            if (threadIdx.x < o) red[threadIdx.x] += red[threadIdx.x + o];
            __syncthreads();
        }
        if (threadIdx.x == 0) {
            out[0] = -red[0];
            g_count = 0;    // reset for next graph replay (determinism)
        }
    }
}

extern "C" void kernel_launch(void* const* d_in, const int* in_sizes, int n_in,
                              void* d_out, int out_size) {
    const float* emb      = (const float*)d_in[0];
    const int*   centers  = (const int*)  d_in[1];
    const int*   contexts = (const int*)  d_in[2];
    const int*   negs     = (const int*)  d_in[3];
    float*       out      = (float*)d_out;

    sg_fused<<<NBLOCKS, THREADS>>>(emb, centers, contexts, negs, out);
}

// round 12
// speedup vs baseline: 1.0175x; 1.0175x over previous
#include <cuda_runtime.h>
#include <cstdint>

#define BATCH 16384
#define NEG 5
#define ROWS 7                                   // u, v, 5 negs
#define WARPS 4
#define THREADS (WARPS * 32)                     // 128
#define EPW 8                                    // elements per warp (sequential)
#define EPB (WARPS * EPW)                        // 32 per block
#define NBLOCKS (BATCH / EPB)                    // 512

__device__ float g_partials[NBLOCKS];
__device__ unsigned int g_count;                 // zero-init; last block resets

__device__ __forceinline__ float logsig(float x) {
    return fminf(x, 0.0f) - log1pf(expf(-fabsf(x)));
}

__device__ __forceinline__ void cp_row(uint32_t dst_base, int slot,
                                       const float4* src, int lane) {
    uint32_t dst = dst_base + (uint32_t)slot * 512 + lane * 16;
    asm volatile("cp.async.cg.shared.global [%0], [%1], 16;\n"
                 :: "r"(dst), "l"(src + lane));
}

__global__ void __launch_bounds__(THREADS)
sg_fused(const float* __restrict__ emb,
         const int* __restrict__ centers,
         const int* __restrict__ contexts,
         const int* __restrict__ negs,
         float* __restrict__ out) {
    // [warp][buf][row][lane] float4 : 4 * 2 * 7 * 512B = 28 KB
    __shared__ __align__(16) float4 stage[WARPS][2][ROWS][32];
    __shared__ float smw[WARPS];
    __shared__ bool is_last;

    const int lane = threadIdx.x & 31;
    const int warp = threadIdx.x >> 5;
    // warp handles elements [base, base+EPW)
    const int base = blockIdx.x * EPB + warp * EPW;

    const float4* e4 = reinterpret_cast<const float4*>(emb);
    const uint32_t st_base =
        (uint32_t)__cvta_generic_to_shared(&stage[warp][0][0][0]);

    // --- fetch indices for element e into lanes 0..6, broadcast, issue rows ---
    auto issue_elem = [&](int e, int buf) {
        const int b = base + e;
        int idx = 0;
        if (lane == 0)      idx = centers[b];
        else if (lane == 1) idx = contexts[b];
        else if (lane < 7)  idx = negs[b * NEG + (lane - 2)];
        const uint32_t dst = st_base + (uint32_t)buf * (ROWS * 512);
        #pragma unroll
        for (int r = 0; r < ROWS; r++) {
            int row = __shfl_sync(0xffffffffu, idx, r);
            cp_row(dst, r, e4 + (size_t)row * 32, lane);
        }
        asm volatile("cp.async.commit_group;\n");
    };

    float acc = 0.0f;

    issue_elem(0, 0);                    // prologue: element 0 in flight

    #pragma unroll
    for (int e = 0; e < EPW; e++) {
        if (e + 1 < EPW) {
            issue_elem(e + 1, (e + 1) & 1);   // keep next element in flight
            asm volatile("cp.async.wait_group 1;\n" ::: "memory");
        } else {
            asm volatile("cp.async.wait_group 0;\n" ::: "memory");
        }
        __syncwarp();

        const float4* st = &stage[warp][e & 1][0][0];
        const float4 u  = st[0 * 32 + lane];
        const float4 v  = st[1 * 32 + lane];
        const float4 w0 = st[2 * 32 + lane];
        const float4 w1 = st[3 * 32 + lane];
        const float4 w2 = st[4 * 32 + lane];
        const float4 w3 = st[5 * 32 + lane];
        const float4 w4 = st[6 * 32 + lane];

        float4 ns;
        ns.x = w0.x + w1.x + w2.x + w3.x + w4.x;
        ns.y = w0.y + w1.y + w2.y + w3.y + w4.y;
        ns.z = w0.z + w1.z + w2.z + w3.z + w4.z;
        ns.w = w0.w + w1.w + w2.w + w3.w + w4.w;

        float pos = u.x * v.x  + u.y * v.y  + u.z * v.z  + u.w * v.w;
        float neg = u.x * ns.x + u.y * ns.y + u.z * ns.z + u.w * ns.w;

        #pragma unroll
        for (int o = 16; o > 0; o >>= 1) {
            pos += __shfl_xor_sync(0xffffffffu, pos, o);
            neg += __shfl_xor_sync(0xffffffffu, neg, o);
        }
        if (lane == 0)
            acc += logsig(pos) + logsig(-neg);

        __syncwarp();   // all lanes done reading buf before it is refilled
    }

    if (lane == 0) smw[warp] = acc;
    __syncthreads();

    if (threadIdx.x == 0) {
        float s = smw[0] + smw[1] + smw[2] + smw[3];
        g_partials[blockIdx.x] = s;
        __threadfence();
        unsigned int c = atomicAdd(&g_count, 1u);
        is_last = (c == NBLOCKS - 1);
    }
    __syncthreads();

    // Last block: deterministic fixed-order reduction of 512 partials.
    if (is_last) {
        __shared__ float red[THREADS];
        float s = 0.0f;
        #pragma unroll
        for (int i = 0; i < NBLOCKS / THREADS; i++)      // 4 per thread
            s += g_partials[threadIdx.x + i * THREADS];
        red[threadIdx.x] = s;
        __syncthreads();
        #pragma unroll
        for (int o = THREADS / 2; o > 0; o >>= 1) {
            if (threadIdx.x < o) red[threadIdx.x] += red[threadIdx.x + o];
            __syncthreads();
        }
        if (threadIdx.x == 0) {
            out[0] = -red[0];
            g_count = 0;    // reset for next graph replay (determinism)
        }
    }
}

extern "C" void kernel_launch(void* const* d_in, const int* in_sizes, int n_in,
                              void* d_out, int out_size) {
    const float* emb      = (const float*)d_in[0];
    const int*   centers  = (const int*)  d_in[1];
    const int*   contexts = (const int*)  d_in[2];
    const int*   negs     = (const int*)  d_in[3];
    float*       out      = (float*)d_out;

    sg_fused<<<NBLOCKS, THREADS>>>(emb, centers, contexts, negs, out);
}